// round 7
// baseline (speedup 1.0000x reference)
#include <cuda_runtime.h>

#define BATCH 4
#define CH    64
#define HH    128
#define WW    128
#define HW    (HH*WW)
#define J18   18
#define CK    576   /* CH*9 */

// Device-global scratch
__device__ float g_xt[BATCH*HW*CH];          // x NHWC [b][h][w][c]      16 MB
__device__ float g_off[BATCH*HW*J18];        // offsets [b][h][w][j]     4.5 MB
__device__ float g_wT2[CK*CH*2];             // W dup: [k][o*2 dup]      294 KB
__device__ float g_s[(size_t)BATCH*HH*CK*WW];// S [b][h][k][w]           151 MB

__device__ __forceinline__ void fma2(unsigned long long& a,
                                     unsigned long long b,
                                     unsigned long long c) {
    asm("fma.rn.f32x2 %0, %1, %2, %0;" : "+l"(a) : "l"(b), "l"(c));
}
__device__ __forceinline__ unsigned long long dup2(float v) {
    unsigned long long r;
    asm("mov.b64 %0, {%1,%1};" : "=l"(r) : "f"(v));
    return r;
}
__device__ __forceinline__ unsigned long long pack2(float a, float b) {
    unsigned long long r;
    asm("mov.b64 %0, {%1,%2};" : "=l"(r) : "f"(a), "f"(b));
    return r;
}
__device__ __forceinline__ void unpack2(unsigned long long v, float& a, float& b) {
    asm("mov.b64 {%0,%1}, %2;" : "=f"(a), "=f"(b) : "l"(v));
}

// ---------------------------------------------------------------------------
// Repack main weight: [o][c][tap] -> [k=tap*64+c][o duplicated x2]
// ---------------------------------------------------------------------------
__global__ void k_prep_wT(const float* __restrict__ weight) {
    int i = blockIdx.x * 256 + threadIdx.x;
    if (i >= CK * CH) return;
    int o = i & 63, k = i >> 6;       // k = tap*64 + c
    int tap = k >> 6, c = k & 63;
    float v = weight[(o * CH + c) * 9 + tap];
    *(float2*)(g_wT2 + (size_t)k * 128 + o * 2) = make_float2(v, v);
}

// ---------------------------------------------------------------------------
// NCHW -> NHWC transpose of x
// ---------------------------------------------------------------------------
__global__ void k_transpose(const float* __restrict__ x) {
    __shared__ float t[32][33];
    int b  = blockIdx.z;
    int c0 = blockIdx.y * 32;
    int p0 = blockIdx.x * 32;
    int tx = threadIdx.x, ty = threadIdx.y;   // 32 x 8
    const float* xb = x + (size_t)b * CH * HW;
#pragma unroll
    for (int i = 0; i < 4; i++)
        t[ty + i * 8][tx] = xb[(c0 + ty + i * 8) * HW + p0 + tx];
    __syncthreads();
    float* dst = g_xt + (size_t)b * HW * CH;
#pragma unroll
    for (int i = 0; i < 4; i++)
        dst[(p0 + ty + i * 8) * CH + c0 + tx] = t[tx][ty + i * 8];
}

// ---------------------------------------------------------------------------
// Offset conv: Conv2d(64 -> 18, 3x3, pad 1) on NCHW x, f32x2 accumulation.
// ---------------------------------------------------------------------------
__global__ void k_offconv(const float* __restrict__ x,
                          const float* __restrict__ w_off,
                          const float* __restrict__ b_off) {
    __shared__ __align__(16) float ws[CH * 9 * 20];
    int tid = threadIdx.y * 32 + threadIdx.x;
    for (int i = tid; i < CH * 9 * J18; i += 128) {
        int j = i % 18; int t = i / 18; int tap = t % 9; int c = t / 9;
        ws[(c * 9 + tap) * 20 + j] = w_off[(j * CH + c) * 9 + tap];
    }
    __syncthreads();

    int b = blockIdx.z;
    int h = blockIdx.y * 4 + threadIdx.y;
    int w = blockIdx.x * 32 + threadIdx.x;

    unsigned long long acc2[9];
#pragma unroll
    for (int q = 0; q < 9; q++)
        acc2[q] = pack2(__ldg(b_off + 2 * q), __ldg(b_off + 2 * q + 1));

    const float* xb = x + (size_t)b * CH * HW;
    for (int c = 0; c < CH; c++) {
        const float* xc = xb + c * HW;
#pragma unroll
        for (int r = 0; r < 3; r++) {
            int y = h + r - 1;
            if ((unsigned)y < (unsigned)HH) {
                const float* xr = xc + y * WW;
                float v0 = (w >= 1)      ? __ldg(xr + w - 1) : 0.f;
                float v1 =                 __ldg(xr + w);
                float v2 = (w < WW - 1)  ? __ldg(xr + w + 1) : 0.f;
                const float* wsr = ws + (c * 9 + r * 3) * 20;
#pragma unroll
                for (int s = 0; s < 3; s++) {
                    float val = (s == 0) ? v0 : ((s == 1) ? v1 : v2);
                    unsigned long long vd = dup2(val);
                    const double2* wp = (const double2*)(wsr + s * 20);
                    double2 p0 = wp[0], p1 = wp[1];
                    double2 p2 = wp[2], p3 = wp[3];
                    double   p4 = *(const double*)(wsr + s * 20 + 16);
                    fma2(acc2[0], vd, __double_as_longlong(p0.x));
                    fma2(acc2[1], vd, __double_as_longlong(p0.y));
                    fma2(acc2[2], vd, __double_as_longlong(p1.x));
                    fma2(acc2[3], vd, __double_as_longlong(p1.y));
                    fma2(acc2[4], vd, __double_as_longlong(p2.x));
                    fma2(acc2[5], vd, __double_as_longlong(p2.y));
                    fma2(acc2[6], vd, __double_as_longlong(p3.x));
                    fma2(acc2[7], vd, __double_as_longlong(p3.y));
                    fma2(acc2[8], vd, __double_as_longlong(p4));
                }
            }
        }
    }

    __syncthreads();
#pragma unroll
    for (int q = 0; q < 9; q++) {
        float a, bb;
        unpack2(acc2[q], a, bb);
        ws[threadIdx.y * 576 + threadIdx.x * 18 + 2 * q]     = a;
        ws[threadIdx.y * 576 + threadIdx.x * 18 + 2 * q + 1] = bb;
    }
    __syncthreads();
    for (int i = tid; i < 4 * 576; i += 128) {
        int row = i / 576, col = i % 576;
        int h2 = blockIdx.y * 4 + row;
        g_off[((size_t)b * HW + h2 * WW + blockIdx.x * 32) * 18 + col] = ws[row * 576 + col];
    }
}

// ---------------------------------------------------------------------------
// Gather kernel: CTA = one (b, h) image row, builds S[576][128] to global.
// Lanes on channels -> coalesced corner loads; transpose via XOR-swizzled
// smem stage (conflict-free STS.128/LDS.128); coalesced 512B row writes.
// ---------------------------------------------------------------------------
#define SMEM_GATHER (1152*32 + 64*128*4)   /* coords 36864 + stage 32768 */

__global__ void __launch_bounds__(256) k_gather() {
    extern __shared__ __align__(16) float sm[];
    int4*   sIdx  = (int4*)sm;               // [1152] = [tap][w]
    float4* sWt   = (float4*)(sm + 1152 * 4);
    float*  stage = sm + 1152 * 8;           // [64 c][32 f4 slots] swizzled

    int h = blockIdx.x, b = blockIdx.y;
    int tid = threadIdx.x, warp = tid >> 5, lane = tid & 31;
    const float* xt = g_xt + (size_t)b * HW * CH;

    // ---- bilinear coords for 9 taps x 128 w ----
    for (int i = tid; i < 1152; i += 256) {
        int tap = i >> 7, w = i & 127;
        const float* op = g_off + ((size_t)b * HW + h * WW + w) * 18 + tap * 2;
        float dy = __ldg(op), dx = __ldg(op + 1);
        float py  = (float)(h + tap / 3 - 1) + dy;
        float pxf = (float)(w + tap % 3 - 1) + dx;
        float fy = floorf(py), fx = floorf(pxf);
        int y0 = (int)fy, x0 = (int)fx;
        float ly = py - fy, lx = pxf - fx;
        float hy = 1.f - ly, hx = 1.f - lx;
        float my0 = ((unsigned)y0       < (unsigned)HH) ? 1.f : 0.f;
        float my1 = ((unsigned)(y0 + 1) < (unsigned)HH) ? 1.f : 0.f;
        float mx0 = ((unsigned)x0       < (unsigned)WW) ? 1.f : 0.f;
        float mx1 = ((unsigned)(x0 + 1) < (unsigned)WW) ? 1.f : 0.f;
        int y0c = min(max(y0, 0), HH - 1);
        int y1c = min(max(y0 + 1, 0), HH - 1);
        int x0c = min(max(x0, 0), WW - 1);
        int x1c = min(max(x0 + 1, 0), WW - 1);
        sIdx[i] = make_int4((y0c * WW + x0c) * CH, (y0c * WW + x1c) * CH,
                            (y1c * WW + x0c) * CH, (y1c * WW + x1c) * CH);
        sWt[i]  = make_float4(hy * hx * my0 * mx0, hy * lx * my0 * mx1,
                              ly * hx * my1 * mx0, ly * lx * my1 * mx1);
    }
    __syncthreads();

    float* gs = g_s + ((size_t)b * HH + h) * (CK * WW);

    for (int t = 0; t < 9; t++) {
        // gather: 64 tasks = (chalf 2) x (wblk 16) over 8 warps
        for (int task = warp; task < 64; task += 8) {
            int chalf = task & 1, wblk = task >> 1;
            int c = chalf * 32 + lane;
            const float* xc = xt + c;
            float rv[4];
#pragma unroll
            for (int i = 0; i < 4; i++) {
                int e = t * 128 + wblk * 4 + i;
                int4   ix = sIdx[e];
                float4 wt = sWt[e];
                rv[i] = wt.x * __ldg(xc + ix.x) + wt.y * __ldg(xc + ix.y)
                      + wt.z * __ldg(xc + ix.z) + wt.w * __ldg(xc + ix.w);
            }
            int slot = wblk ^ (c & 7);
            *(float4*)(stage + c * 128 + slot * 4) =
                make_float4(rv[0], rv[1], rv[2], rv[3]);
        }
        __syncthreads();
        // write out: 64 k-rows x 128 w, coalesced
#pragma unroll
        for (int j = 0; j < 8; j++) {
            int lin = j * 256 + tid;      // float4 index (2048 total)
            int r = lin >> 5, col = lin & 31;
            float4 v = *(float4*)(stage + r * 128 + col * 4);
            int wb = col ^ (r & 7);
            *(float4*)(gs + ((size_t)(t * 64 + r)) * 128 + wb * 4) = v;
        }
        __syncthreads();
    }
}

// ---------------------------------------------------------------------------
// GEMM kernel: per (b,h): C[64 o][128 w] = W[64][576] * S[576][128].
// S streamed in 32KB k-chunks via cp.async double-buffer. W pre-duplicated
// -> double2 loads are direct f32x2 operands (no dup movs).
// Thread tile: 8 o x 4 w (16 fma2 per k).
// ---------------------------------------------------------------------------
#define KCHUNK 64
#define SMEM_GEMM (2 * KCHUNK * 128 * 4)   /* 65536 */

__global__ void __launch_bounds__(256) k_gemm(float* __restrict__ out) {
    extern __shared__ __align__(16) float sb[];
    int h = blockIdx.x, b = blockIdx.y;
    int tid = threadIdx.x;
    int o_grp = tid & 7, px_grp = tid >> 3;

    const float* gs = g_s + ((size_t)b * HH + h) * (CK * WW);
    unsigned sbase = (unsigned)__cvta_generic_to_shared(sb);

    // prefetch chunk 0
#pragma unroll
    for (int i = 0; i < 8; i++) {
        int idx = tid + i * 256;
        asm volatile("cp.async.cg.shared.global [%0], [%1], 16;"
                     :: "r"(sbase + idx * 16), "l"(gs + idx * 4));
    }
    asm volatile("cp.async.commit_group;");

    unsigned long long acc[8][2];
#pragma unroll
    for (int i = 0; i < 8; i++) { acc[i][0] = 0ULL; acc[i][1] = 0ULL; }

    const float* wbase = g_wT2 + o_grp * 16;

    for (int ch = 0; ch < 9; ch++) {
        int buf = ch & 1;
        if (ch < 8) {
            int nbuf = buf ^ 1;
            const float* src = gs + (size_t)(ch + 1) * KCHUNK * 128;
#pragma unroll
            for (int i = 0; i < 8; i++) {
                int idx = tid + i * 256;
                asm volatile("cp.async.cg.shared.global [%0], [%1], 16;"
                             :: "r"(sbase + nbuf * 32768 + idx * 16),
                                "l"(src + idx * 4));
            }
            asm volatile("cp.async.commit_group;");
            asm volatile("cp.async.wait_group 1;");
        } else {
            asm volatile("cp.async.wait_group 0;");
        }
        __syncthreads();

        const float* wrow = wbase + (size_t)ch * KCHUNK * 128;
        unsigned sS = sbase + buf * 32768 + px_grp * 16;
#pragma unroll 4
        for (int k = 0; k < KCHUNK; k++) {
            double2 w01 = *(const double2*)(wrow + k * 128);
            double2 w23 = *(const double2*)(wrow + k * 128 + 4);
            double2 w45 = *(const double2*)(wrow + k * 128 + 8);
            double2 w67 = *(const double2*)(wrow + k * 128 + 12);
            unsigned long long s01, s23;
            asm("ld.shared.v2.b64 {%0,%1},[%2];"
                : "=l"(s01), "=l"(s23) : "r"(sS + k * 512));
            fma2(acc[0][0], __double_as_longlong(w01.x), s01);
            fma2(acc[0][1], __double_as_longlong(w01.x), s23);
            fma2(acc[1][0], __double_as_longlong(w01.y), s01);
            fma2(acc[1][1], __double_as_longlong(w01.y), s23);
            fma2(acc[2][0], __double_as_longlong(w23.x), s01);
            fma2(acc[2][1], __double_as_longlong(w23.x), s23);
            fma2(acc[3][0], __double_as_longlong(w23.y), s01);
            fma2(acc[3][1], __double_as_longlong(w23.y), s23);
            fma2(acc[4][0], __double_as_longlong(w45.x), s01);
            fma2(acc[4][1], __double_as_longlong(w45.x), s23);
            fma2(acc[5][0], __double_as_longlong(w45.y), s01);
            fma2(acc[5][1], __double_as_longlong(w45.y), s23);
            fma2(acc[6][0], __double_as_longlong(w67.x), s01);
            fma2(acc[6][1], __double_as_longlong(w67.x), s23);
            fma2(acc[7][0], __double_as_longlong(w67.y), s01);
            fma2(acc[7][1], __double_as_longlong(w67.y), s23);
        }
        __syncthreads();
    }

    // write out: 8 rows (o), 4 w each
    int o0 = o_grp * 8, w0 = px_grp * 4;
    float* __restrict__ ob = out + (((size_t)b * CH + o0) * HH + h) * WW + w0;
#pragma unroll
    for (int i = 0; i < 8; i++) {
        float r0, r1, r2, r3;
        unpack2(acc[i][0], r0, r1);
        unpack2(acc[i][1], r2, r3);
        *(float4*)(ob + (size_t)i * HW) = make_float4(r0, r1, r2, r3);
    }
}

// ---------------------------------------------------------------------------
extern "C" void kernel_launch(void* const* d_in, const int* in_sizes, int n_in,
                              void* d_out, int out_size) {
    const float* x      = (const float*)d_in[0];
    const float* w_off  = (const float*)d_in[1];
    const float* b_off  = (const float*)d_in[2];
    const float* weight = (const float*)d_in[3];
    float* out = (float*)d_out;

    cudaFuncSetAttribute(k_gather, cudaFuncAttributeMaxDynamicSharedMemorySize,
                         SMEM_GATHER);
    cudaFuncSetAttribute(k_gemm, cudaFuncAttributeMaxDynamicSharedMemorySize,
                         SMEM_GEMM);

    k_prep_wT<<<(CK * CH + 255) / 256, 256>>>(weight);
    k_transpose<<<dim3(HW / 32, CH / 32, BATCH), dim3(32, 8)>>>(x);
    k_offconv<<<dim3(WW / 32, HH / 4, BATCH), dim3(32, 4)>>>(x, w_off, b_off);
    k_gather<<<dim3(HH, BATCH), 256, SMEM_GATHER>>>();
    k_gemm<<<dim3(HH, BATCH), 256, SMEM_GEMM>>>(out);
}

// round 9
// speedup vs baseline: 2.4288x; 2.4288x over previous
#include <cuda_runtime.h>

#define BATCH 4
#define CH    64
#define HH    128
#define WW    128
#define HW    (HH*WW)
#define J18   18
#define CK    576   /* CH*9 */

// Device-global scratch
__device__ float g_xt[BATCH*HW*CH];    // x NHWC [b][h][w][c]   16 MB
__device__ float g_off[BATCH*HW*J18];  // offsets [b][h][w][j]  4.5 MB
__device__ float g_wT[CK*CH];          // W [k=tap*64+c][o]     147 KB

__device__ __forceinline__ void fma2(unsigned long long& a,
                                     unsigned long long b,
                                     unsigned long long c) {
    asm("fma.rn.f32x2 %0, %1, %2, %0;" : "+l"(a) : "l"(b), "l"(c));
}
__device__ __forceinline__ unsigned long long dup2(float v) {
    unsigned long long r;
    asm("mov.b64 %0, {%1,%1};" : "=l"(r) : "f"(v));
    return r;
}
__device__ __forceinline__ unsigned long long pack2(float a, float b) {
    unsigned long long r;
    asm("mov.b64 %0, {%1,%2};" : "=l"(r) : "f"(a), "f"(b));
    return r;
}
__device__ __forceinline__ void unpack2(unsigned long long v, float& a, float& b) {
    asm("mov.b64 {%0,%1}, %2;" : "=f"(a), "=f"(b) : "l"(v));
}

// ---------------------------------------------------------------------------
// Repack main weight: [o][c][tap] -> [k=tap*64+c][o]
// ---------------------------------------------------------------------------
__global__ void k_prep_wT(const float* __restrict__ weight) {
    int i = blockIdx.x * 256 + threadIdx.x;
    if (i >= CK * CH) return;
    int o = i & 63, k = i >> 6;
    int tap = k >> 6, c = k & 63;
    g_wT[k * 64 + o] = weight[(o * CH + c) * 9 + tap];
}

// ---------------------------------------------------------------------------
// NCHW -> NHWC transpose of x
// ---------------------------------------------------------------------------
__global__ void k_transpose(const float* __restrict__ x) {
    __shared__ float t[32][33];
    int b  = blockIdx.z;
    int c0 = blockIdx.y * 32;
    int p0 = blockIdx.x * 32;
    int tx = threadIdx.x, ty = threadIdx.y;   // 32 x 8
    const float* xb = x + (size_t)b * CH * HW;
#pragma unroll
    for (int i = 0; i < 4; i++)
        t[ty + i * 8][tx] = xb[(c0 + ty + i * 8) * HW + p0 + tx];
    __syncthreads();
    float* dst = g_xt + (size_t)b * HW * CH;
#pragma unroll
    for (int i = 0; i < 4; i++)
        dst[(p0 + ty + i * 8) * CH + c0 + tx] = t[tx][ty + i * 8];
}

// ---------------------------------------------------------------------------
// Offset conv: Conv2d(64 -> 18, 3x3, pad 1) on NCHW x, f32x2 accumulation.
// ---------------------------------------------------------------------------
__global__ void k_offconv(const float* __restrict__ x,
                          const float* __restrict__ w_off,
                          const float* __restrict__ b_off) {
    __shared__ __align__(16) float ws[CH * 9 * 20];
    int tid = threadIdx.y * 32 + threadIdx.x;
    for (int i = tid; i < CH * 9 * J18; i += 128) {
        int j = i % 18; int t = i / 18; int tap = t % 9; int c = t / 9;
        ws[(c * 9 + tap) * 20 + j] = w_off[(j * CH + c) * 9 + tap];
    }
    __syncthreads();

    int b = blockIdx.z;
    int h = blockIdx.y * 4 + threadIdx.y;
    int w = blockIdx.x * 32 + threadIdx.x;

    unsigned long long acc2[9];
#pragma unroll
    for (int q = 0; q < 9; q++)
        acc2[q] = pack2(__ldg(b_off + 2 * q), __ldg(b_off + 2 * q + 1));

    const float* xb = x + (size_t)b * CH * HW;
    for (int c = 0; c < CH; c++) {
        const float* xc = xb + c * HW;
#pragma unroll
        for (int r = 0; r < 3; r++) {
            int y = h + r - 1;
            if ((unsigned)y < (unsigned)HH) {
                const float* xr = xc + y * WW;
                float v0 = (w >= 1)      ? __ldg(xr + w - 1) : 0.f;
                float v1 =                 __ldg(xr + w);
                float v2 = (w < WW - 1)  ? __ldg(xr + w + 1) : 0.f;
                const float* wsr = ws + (c * 9 + r * 3) * 20;
#pragma unroll
                for (int s = 0; s < 3; s++) {
                    float val = (s == 0) ? v0 : ((s == 1) ? v1 : v2);
                    unsigned long long vd = dup2(val);
                    const double2* wp = (const double2*)(wsr + s * 20);
                    double2 p0 = wp[0], p1 = wp[1];
                    double2 p2 = wp[2], p3 = wp[3];
                    double   p4 = *(const double*)(wsr + s * 20 + 16);
                    fma2(acc2[0], vd, __double_as_longlong(p0.x));
                    fma2(acc2[1], vd, __double_as_longlong(p0.y));
                    fma2(acc2[2], vd, __double_as_longlong(p1.x));
                    fma2(acc2[3], vd, __double_as_longlong(p1.y));
                    fma2(acc2[4], vd, __double_as_longlong(p2.x));
                    fma2(acc2[5], vd, __double_as_longlong(p2.y));
                    fma2(acc2[6], vd, __double_as_longlong(p3.x));
                    fma2(acc2[7], vd, __double_as_longlong(p3.y));
                    fma2(acc2[8], vd, __double_as_longlong(p4));
                }
            }
        }
    }

    __syncthreads();
#pragma unroll
    for (int q = 0; q < 9; q++) {
        float a, bb;
        unpack2(acc2[q], a, bb);
        ws[threadIdx.y * 576 + threadIdx.x * 18 + 2 * q]     = a;
        ws[threadIdx.y * 576 + threadIdx.x * 18 + 2 * q + 1] = bb;
    }
    __syncthreads();
    for (int i = tid; i < 4 * 576; i += 128) {
        int row = i / 576, col = i % 576;
        int h2 = blockIdx.y * 4 + row;
        g_off[((size_t)b * HW + h2 * WW + blockIdx.x * 32) * 18 + col] = ws[row * 576 + col];
    }
}

// ---------------------------------------------------------------------------
// Fused deform+GEMM. CTA = 64 o x 64 px (one 64-wide strip of one row h).
// 128 threads. Per tap: gather S_t[64 c][64 px DUPLICATED {s,s}] into smem
// (XOR-swizzled 512B rows, swizzle key = c & 31 on BOTH sides), then GEMM
// partial: thread tile 8o x 4px, f32x2 pairs over (o,o+1): W pairs load
// directly (no dup movs), S pairs load pre-duplicated (no dup movs).
// smem: S 32KB + idx 9KB + wt 9KB = 50KB -> 4 CTAs/SM.
// ---------------------------------------------------------------------------
#define NPT 576   /* 9 taps x 64 px */
#define SMEM_MAIN (64*128*4 + NPT*16 + NPT*16)   /* 32768+9216+9216=51200 */

__global__ void __launch_bounds__(128) k_main(float* __restrict__ out) {
    extern __shared__ __align__(16) float sm[];
    float*  sS   = sm;                          // [64 c][64 px dup] 512B rows
    int4*   sIdx = (int4*)(sm + 64 * 128);      // [576]
    float4* sWt  = (float4*)(sm + 64 * 128 + NPT * 4);

    int b  = blockIdx.z;
    int h  = blockIdx.y;
    int w0 = blockIdx.x * 64;
    int tid  = threadIdx.x;
    int warp = tid >> 5, lane = tid & 31;

    const float* xt = g_xt + (size_t)b * HW * CH;

    // ---- Precompute bilinear coords: entry e = tap*64 + px ----
    for (int e = tid; e < NPT; e += 128) {
        int tap = e >> 6, px = e & 63;
        int w = w0 + px;
        const float* op = g_off + ((size_t)b * HW + h * WW + w) * 18 + tap * 2;
        float dy = __ldg(op), dx = __ldg(op + 1);
        float py  = (float)(h + tap / 3 - 1) + dy;
        float pxf = (float)(w + tap % 3 - 1) + dx;
        float fy = floorf(py), fx = floorf(pxf);
        int y0 = (int)fy, x0 = (int)fx;
        float ly = py - fy, lx = pxf - fx;
        float hy = 1.f - ly, hx = 1.f - lx;
        float my0 = ((unsigned)y0       < (unsigned)HH) ? 1.f : 0.f;
        float my1 = ((unsigned)(y0 + 1) < (unsigned)HH) ? 1.f : 0.f;
        float mx0 = ((unsigned)x0       < (unsigned)WW) ? 1.f : 0.f;
        float mx1 = ((unsigned)(x0 + 1) < (unsigned)WW) ? 1.f : 0.f;
        int y0c = min(max(y0, 0), HH - 1);
        int y1c = min(max(y0 + 1, 0), HH - 1);
        int x0c = min(max(x0, 0), WW - 1);
        int x1c = min(max(x0 + 1, 0), WW - 1);
        sIdx[e] = make_int4((y0c * WW + x0c) * CH, (y0c * WW + x1c) * CH,
                            (y1c * WW + x0c) * CH, (y1c * WW + x1c) * CH);
        sWt[e]  = make_float4(hy * hx * my0 * mx0, hy * lx * my0 * mx1,
                              ly * hx * my1 * mx0, ly * lx * my1 * mx1);
    }
    __syncthreads();

    int o_grp = tid & 7, px_grp = tid >> 3;     // 8 o-groups x 16 px-groups
    int o_base = o_grp * 8;
    unsigned long long acc[4][4];
#pragma unroll
    for (int p = 0; p < 4; p++)
#pragma unroll
        for (int j = 0; j < 4; j++) acc[p][j] = 0ULL;

    for (int tap = 0; tap < 9; tap++) {
        // ---- Gather: 32 tasks = 16 px-groups x 2 chan-halves ----
        for (int task = warp; task < 32; task += 4) {
            int chalf = task & 1, pxg = task >> 1;
            int c = chalf * 32 + lane;
            const float* xc = xt + c;
            float rv[4];
#pragma unroll
            for (int i = 0; i < 4; i++) {
                int e = tap * 64 + pxg * 4 + i;
                int4   ix = sIdx[e];
                float4 wt = sWt[e];
                rv[i] = wt.x * __ldg(xc + ix.x) + wt.y * __ldg(xc + ix.y)
                      + wt.z * __ldg(xc + ix.z) + wt.w * __ldg(xc + ix.w);
            }
            float4* row = (float4*)(sS + c * 128);   // 32 slots of 16B
            int key = c & 31;
            row[(pxg * 2)     ^ key] = make_float4(rv[0], rv[0], rv[1], rv[1]);
            row[(pxg * 2 + 1) ^ key] = make_float4(rv[2], rv[2], rv[3], rv[3]);
        }
        __syncthreads();

        // ---- GEMM partial over 64 k (= channels of this tap) ----
        const float* wtap = g_wT + (size_t)(tap * 64) * 64 + o_base;
        int pp0 = px_grp * 2;
#pragma unroll 4
        for (int k = 0; k < 64; k++) {
            const ulonglong2* w8 = (const ulonglong2*)(wtap + k * 64);
            ulonglong2 wA = __ldg(w8);        // pairs (o0,o1),(o2,o3)
            ulonglong2 wB = __ldg(w8 + 1);    // pairs (o4,o5),(o6,o7)
            const ulonglong2* srow = (const ulonglong2*)(sS + k * 128);
            int key = k & 31;                 // matches store-side swizzle
            ulonglong2 sA = srow[pp0 ^ key];        // {s0,s0},{s1,s1}
            ulonglong2 sB = srow[(pp0 + 1) ^ key];  // {s2,s2},{s3,s3}
            fma2(acc[0][0], wA.x, sA.x); fma2(acc[0][1], wA.x, sA.y);
            fma2(acc[0][2], wA.x, sB.x); fma2(acc[0][3], wA.x, sB.y);
            fma2(acc[1][0], wA.y, sA.x); fma2(acc[1][1], wA.y, sA.y);
            fma2(acc[1][2], wA.y, sB.x); fma2(acc[1][3], wA.y, sB.y);
            fma2(acc[2][0], wB.x, sA.x); fma2(acc[2][1], wB.x, sA.y);
            fma2(acc[2][2], wB.x, sB.x); fma2(acc[2][3], wB.x, sB.y);
            fma2(acc[3][0], wB.y, sA.x); fma2(acc[3][1], wB.y, sA.y);
            fma2(acc[3][2], wB.y, sB.x); fma2(acc[3][3], wB.y, sB.y);
        }
        __syncthreads();
    }

    // ---- Epilogue: 8 output rows (o), 4 px each ----
    int w = w0 + px_grp * 4;
    float* ob = out + (((size_t)b * CH + o_base) * HH + h) * WW + w;
#pragma unroll
    for (int p = 0; p < 4; p++) {
        float e0, d0, e1, d1, e2, d2, e3, d3;
        unpack2(acc[p][0], e0, d0);
        unpack2(acc[p][1], e1, d1);
        unpack2(acc[p][2], e2, d2);
        unpack2(acc[p][3], e3, d3);
        *(float4*)(ob + (size_t)(2 * p) * HW)     = make_float4(e0, e1, e2, e3);
        *(float4*)(ob + (size_t)(2 * p + 1) * HW) = make_float4(d0, d1, d2, d3);
    }
}

// ---------------------------------------------------------------------------
extern "C" void kernel_launch(void* const* d_in, const int* in_sizes, int n_in,
                              void* d_out, int out_size) {
    const float* x      = (const float*)d_in[0];
    const float* w_off  = (const float*)d_in[1];
    const float* b_off  = (const float*)d_in[2];
    const float* weight = (const float*)d_in[3];
    float* out = (float*)d_out;

    cudaFuncSetAttribute(k_main, cudaFuncAttributeMaxDynamicSharedMemorySize,
                         SMEM_MAIN);

    k_prep_wT<<<(CK * CH + 255) / 256, 256>>>(weight);
    k_transpose<<<dim3(HW / 32, CH / 32, BATCH), dim3(32, 8)>>>(x);
    k_offconv<<<dim3(WW / 32, HH / 4, BATCH), dim3(32, 4)>>>(x, w_off, b_off);
    k_main<<<dim3(WW / 64, HH, BATCH), 128, SMEM_MAIN>>>(out);
}